// round 7
// baseline (speedup 1.0000x reference)
#include <cuda_runtime.h>
#include <math.h>

#define NN    50000
#define NE    800000
#define INF_  32
#define H     64
#define HV    16      // H/4 (float4 lanes per row)
#define EDIM  4
#define NL    3
#define NG    512
#define NOUT  2
#define NPAD  50048   // 782 * 64 = 3128 * 16
#define BN_EPS 1e-5f
#define PN_EPS 1e-5f

// ---------------- persistent device scratch (zero-initialized at load) -----
__device__ float d_h[NPAD * H];
__device__ float d_agg[NPAD * H];
__device__ float d_tmp[NPAD * H];
__device__ float d_gsum[NG * H];
__device__ float d_gss[NG];
__device__ float d_gcnt[NG];
__device__ float d_mean[NG * H];
__device__ float d_invd[NG];
__device__ float d_pool[NG * H];
// CSR build scratch (d_deg must be zero at launch entry; scan re-zeros it)
__device__ int    d_deg[NN];
__device__ int    d_rowptr[NN + 1];
__device__ int    d_fill[NN];
__device__ int    d_srcp[NE];
__device__ float4 d_eap[NE];

// 16-byte vector reduction to global (sm_90+)
__device__ __forceinline__ void red_add4(float4* a, float4 v) {
    asm volatile("red.global.add.v4.f32 [%0], {%1,%2,%3,%4};"
                 :: "l"(a), "f"(v.x), "f"(v.y), "f"(v.z), "f"(v.w) : "memory");
}

__device__ __forceinline__ float4 f4zero() { return make_float4(0.f, 0.f, 0.f, 0.f); }

__device__ __forceinline__ void f4fma(float4& acc, float s, const float4 w) {
    acc.x = fmaf(s, w.x, acc.x);
    acc.y = fmaf(s, w.y, acc.y);
    acc.z = fmaf(s, w.z, acc.z);
    acc.w = fmaf(s, w.w, acc.w);
}

__device__ __forceinline__ float4 f4relu_add(float4 a, float4 b) {
    return make_float4(fmaxf(a.x + b.x, 0.f), fmaxf(a.y + b.y, 0.f),
                       fmaxf(a.z + b.z, 0.f), fmaxf(a.w + b.w, 0.f));
}

// 4x4 register-patch GEMM over 64x64 tile in smem.
__device__ __forceinline__ void gemm64(const float* __restrict__ Ws,
                                       const float* __restrict__ zs,
                                       int rg, int c4, float4 acc[4]) {
    acc[0] = f4zero(); acc[1] = f4zero(); acc[2] = f4zero(); acc[3] = f4zero();
    #pragma unroll
    for (int k4 = 0; k4 < 16; k4++) {
        float4 w0 = *(const float4*)&Ws[(k4 * 4 + 0) * H + c4 * 4];
        float4 w1 = *(const float4*)&Ws[(k4 * 4 + 1) * H + c4 * 4];
        float4 w2 = *(const float4*)&Ws[(k4 * 4 + 2) * H + c4 * 4];
        float4 w3 = *(const float4*)&Ws[(k4 * 4 + 3) * H + c4 * 4];
        float4 z0 = *(const float4*)&zs[(rg * 4 + 0) * H + k4 * 4];
        float4 z1 = *(const float4*)&zs[(rg * 4 + 1) * H + k4 * 4];
        float4 z2 = *(const float4*)&zs[(rg * 4 + 2) * H + k4 * 4];
        float4 z3 = *(const float4*)&zs[(rg * 4 + 3) * H + k4 * 4];
        f4fma(acc[0], z0.x, w0); f4fma(acc[0], z0.y, w1); f4fma(acc[0], z0.z, w2); f4fma(acc[0], z0.w, w3);
        f4fma(acc[1], z1.x, w0); f4fma(acc[1], z1.y, w1); f4fma(acc[1], z1.z, w2); f4fma(acc[1], z1.w, w3);
        f4fma(acc[2], z2.x, w0); f4fma(acc[2], z2.y, w1); f4fma(acc[2], z2.z, w2); f4fma(acc[2], z2.w, w3);
        f4fma(acc[3], z3.x, w0); f4fma(acc[3], z3.y, w1); f4fma(acc[3], z3.z, w2); f4fma(acc[3], z3.w, w3);
    }
}

// ---------------- counts: batch is sorted -> binary search per graph -------
__global__ void count_kernel(const int* __restrict__ batch) {
    int g = blockIdx.x * blockDim.x + threadIdx.x;
    if (g >= NG) return;
    int lo = 0, hi = NN;
    while (lo < hi) { int m = (lo + hi) >> 1; if (batch[m] < g) lo = m + 1; else hi = m; }
    int s = lo;
    lo = 0; hi = NN;
    while (lo < hi) { int m = (lo + hi) >> 1; if (batch[m] < g + 1) lo = m + 1; else hi = m; }
    d_gcnt[g] = fmaxf((float)(lo - s), 1.0f);
}

// ---------------- CSR build: degrees -> scan -> scatter --------------------
__global__ void __launch_bounds__(256) deg_kernel(const int* __restrict__ ei) {
    int e = blockIdx.x * 256 + threadIdx.x;     // exactly NE
    atomicAdd(&d_deg[__ldg(ei + NE + e)], 1);
}

#define SCAN_T  1024
#define CHUNK   49          // 1024*49 = 50176 >= NN
__global__ void __launch_bounds__(SCAN_T) scan_kernel() {
    __shared__ int wsum[32];
    int t = threadIdx.x;
    int base = t * CHUNK;
    int lsum = 0;
    #pragma unroll 1
    for (int i = 0; i < CHUNK; i++) {
        int idx = base + i;
        if (idx < NN) lsum += d_deg[idx];
    }
    int lane = t & 31, wid = t >> 5;
    int inc = lsum;
    #pragma unroll
    for (int o = 1; o < 32; o <<= 1) {
        int n = __shfl_up_sync(0xffffffffu, inc, o);
        if (lane >= o) inc += n;
    }
    if (lane == 31) wsum[wid] = inc;
    __syncthreads();
    if (wid == 0) {
        int v = wsum[lane];
        #pragma unroll
        for (int o = 1; o < 32; o <<= 1) {
            int n = __shfl_up_sync(0xffffffffu, v, o);
            if (lane >= o) v += n;
        }
        wsum[lane] = v;                 // inclusive warp totals
    }
    __syncthreads();
    int run = (wid > 0 ? wsum[wid - 1] : 0) + (inc - lsum);
    #pragma unroll 1
    for (int i = 0; i < CHUNK; i++) {
        int idx = base + i;
        if (idx < NN) {
            int d = d_deg[idx];
            d_rowptr[idx] = run;
            d_fill[idx]   = run;
            run += d;
            d_deg[idx] = 0;             // self-restore for next launch
        }
    }
    if (t == SCAN_T - 1) d_rowptr[NN] = NE;
}

__global__ void __launch_bounds__(256) scatter_kernel(const int* __restrict__ ei,
                                                      const float* __restrict__ eattr) {
    int e = blockIdx.x * 256 + threadIdx.x;     // exactly NE
    int dst = __ldg(ei + NE + e);
    int pos = atomicAdd(&d_fill[dst], 1);
    d_srcp[pos] = __ldg(ei + e);
    d_eap[pos]  = __ldg((const float4*)eattr + e);
}

// ---------------- input linear: h = x @ W_in + b ---------------------------
__global__ void __launch_bounds__(256) lin_in_kernel(const float* __restrict__ x,
                                                     const float* __restrict__ W,
                                                     const float* __restrict__ b) {
    __shared__ __align__(16) float4 Ws[INF_ * HV];
    __shared__ __align__(16) float4 bs[HV];
    int t = threadIdx.x;
    for (int j = t; j < INF_ * HV; j += 256) Ws[j] = ((const float4*)W)[j];
    if (t < HV) bs[t] = ((const float4*)b)[t];
    __syncthreads();

    int lane = t & 15, rloc = t >> 4;
    int row = blockIdx.x * 16 + rloc;

    if (row < NN) {
        float4 acc = bs[lane];
        const float* xr = x + row * INF_;
        #pragma unroll
        for (int k = 0; k < INF_; k++) {
            float xv = __ldg(xr + k);
            f4fma(acc, xv, Ws[k * HV + lane]);
        }
        ((float4*)d_h)[row * HV + lane] = acc;
    }
}

// ---------------- CSR aggregation: agg[v] = sum relu(h[src] + ea@We+be) ----
// 16 threads per node; per edge all lanes broadcast-load src/eattr, gather
// h[src] as one coalesced 256B row. 2-way pipelined. No atomics.
__global__ void __launch_bounds__(256) gine_agg_kernel(const float* __restrict__ eW,
                                                       const float* __restrict__ eb) {
    __shared__ __align__(16) float4 Ws[EDIM * HV];
    __shared__ __align__(16) float4 bs[HV];
    int t = threadIdx.x;
    if (t < EDIM * HV) Ws[t] = ((const float4*)eW)[t];
    if (t < HV) bs[t] = ((const float4*)eb)[t];
    __syncthreads();

    int v    = blockIdx.x * 16 + (t >> 4);   // v < NPAD (3128 blocks)
    int lane = t & 15;
    float4 w0 = Ws[0 * HV + lane], w1 = Ws[1 * HV + lane];
    float4 w2 = Ws[2 * HV + lane], w3 = Ws[3 * HV + lane];
    float4 bv = bs[lane];

    int start = 0, end = 0;
    if (v < NN) { start = __ldg(&d_rowptr[v]); end = __ldg(&d_rowptr[v + 1]); }

    float4 acc = f4zero();
    int j = start;
    for (; j + 2 <= end; j += 2) {
        int s0 = __ldg(&d_srcp[j]);
        int s1 = __ldg(&d_srcp[j + 1]);
        float4 e0 = __ldg(&d_eap[j]);
        float4 e1 = __ldg(&d_eap[j + 1]);
        float4 h0 = __ldg((const float4*)d_h + s0 * HV + lane);
        float4 h1 = __ldg((const float4*)d_h + s1 * HV + lane);
        float4 v0 = bv;
        f4fma(v0, e0.x, w0); f4fma(v0, e0.y, w1); f4fma(v0, e0.z, w2); f4fma(v0, e0.w, w3);
        float4 v1 = bv;
        f4fma(v1, e1.x, w0); f4fma(v1, e1.y, w1); f4fma(v1, e1.z, w2); f4fma(v1, e1.w, w3);
        float4 m0 = f4relu_add(v0, h0);
        float4 m1 = f4relu_add(v1, h1);
        acc.x += m0.x + m1.x; acc.y += m0.y + m1.y;
        acc.z += m0.z + m1.z; acc.w += m0.w + m1.w;
    }
    if (j < end) {
        int s0 = __ldg(&d_srcp[j]);
        float4 e0 = __ldg(&d_eap[j]);
        float4 h0 = __ldg((const float4*)d_h + s0 * HV + lane);
        float4 v0 = bv;
        f4fma(v0, e0.x, w0); f4fma(v0, e0.y, w1); f4fma(v0, e0.z, w2); f4fma(v0, e0.w, w3);
        float4 m0 = f4relu_add(v0, h0);
        acc.x += m0.x; acc.y += m0.y; acc.z += m0.z; acc.w += m0.w;
    }
    ((float4*)d_agg)[v * HV + lane] = acc;   // padded v writes zeros
}

// ---------------- MLP stage 1: d_tmp = relu(BN1(z @ W1 + b1)) --------------
__global__ void __launch_bounds__(256) mlp1_kernel(
    const float* __restrict__ W1, const float* __restrict__ b1,
    const float* __restrict__ g1, const float* __restrict__ be1,
    const float* __restrict__ rm1, const float* __restrict__ rv1,
    const float* __restrict__ epsp)
{
    __shared__ __align__(16) float Ws[H * H];
    __shared__ __align__(16) float zs[64 * H];

    int t = threadIdx.x;
    int c4 = t & 15, rg = t >> 4;
    int c0 = c4 * 4;
    int R0 = blockIdx.x * 64;

    float4 wv[4];
    #pragma unroll
    for (int s = 0; s < 4; s++) wv[s] = __ldg((const float4*)W1 + t + 256 * s);

    float4 gv  = __ldg((const float4*)(g1 + c0));
    float4 rvv = __ldg((const float4*)(rv1 + c0));
    float4 bv  = __ldg((const float4*)(b1 + c0));
    float4 bev = __ldg((const float4*)(be1 + c0));
    float4 rmv = __ldg((const float4*)(rm1 + c0));
    float epv = 1.0f + __ldg(epsp);

    float4 zst[4];
    #pragma unroll
    for (int s = 0; s < 4; s++) {
        int gi = R0 * HV + t + 256 * s;
        float4 hv = __ldg((const float4*)d_h + gi);
        float4 av = __ldg((const float4*)d_agg + gi);
        zst[s] = make_float4(fmaf(epv, hv.x, av.x), fmaf(epv, hv.y, av.y),
                             fmaf(epv, hv.z, av.z), fmaf(epv, hv.w, av.w));
    }

    float4 sc, bb;
    sc.x = gv.x * rsqrtf(rvv.x + BN_EPS);
    sc.y = gv.y * rsqrtf(rvv.y + BN_EPS);
    sc.z = gv.z * rsqrtf(rvv.z + BN_EPS);
    sc.w = gv.w * rsqrtf(rvv.w + BN_EPS);
    bb.x = fmaf(bv.x - rmv.x, sc.x, bev.x);
    bb.y = fmaf(bv.y - rmv.y, sc.y, bev.y);
    bb.z = fmaf(bv.z - rmv.z, sc.z, bev.z);
    bb.w = fmaf(bv.w - rmv.w, sc.w, bev.w);

    #pragma unroll
    for (int s = 0; s < 4; s++) {
        float4 w = wv[s];
        w.x *= sc.x; w.y *= sc.y; w.z *= sc.z; w.w *= sc.w;
        ((float4*)Ws)[t + 256 * s] = w;
        ((float4*)zs)[t + 256 * s] = zst[s];
    }
    __syncthreads();

    float4 acc[4];
    gemm64(Ws, zs, rg, c4, acc);

    int row0 = R0 + rg * 4;
    #pragma unroll
    for (int r = 0; r < 4; r++) {
        int row = row0 + r;
        if (row < NN) ((float4*)d_tmp)[row * HV + c4] = f4relu_add(acc[r], bb);
    }
}

// ---------------- MLP stage 2: d_h = relu(BN2(y @ W2 + b2)) + PN stats -----
__global__ void __launch_bounds__(256) mlp2_kernel(
    const float* __restrict__ W2, const float* __restrict__ b2,
    const float* __restrict__ g2, const float* __restrict__ be2,
    const float* __restrict__ rm2, const float* __restrict__ rv2,
    const int* __restrict__ batch, int do_pn)
{
    __shared__ __align__(16) float Ws[H * H];
    __shared__ __align__(16) float zs[64 * H];

    int t = threadIdx.x;
    int c4 = t & 15, rg = t >> 4;
    int c0 = c4 * 4;
    int R0 = blockIdx.x * 64;

    float4 wv[4];
    #pragma unroll
    for (int s = 0; s < 4; s++) wv[s] = __ldg((const float4*)W2 + t + 256 * s);

    float4 gv  = __ldg((const float4*)(g2 + c0));
    float4 rvv = __ldg((const float4*)(rv2 + c0));
    float4 bv  = __ldg((const float4*)(b2 + c0));
    float4 bev = __ldg((const float4*)(be2 + c0));
    float4 rmv = __ldg((const float4*)(rm2 + c0));

    float4 zst[4];
    #pragma unroll
    for (int s = 0; s < 4; s++)
        zst[s] = __ldg((const float4*)d_tmp + R0 * HV + t + 256 * s);

    float4 sc, bb;
    sc.x = gv.x * rsqrtf(rvv.x + BN_EPS);
    sc.y = gv.y * rsqrtf(rvv.y + BN_EPS);
    sc.z = gv.z * rsqrtf(rvv.z + BN_EPS);
    sc.w = gv.w * rsqrtf(rvv.w + BN_EPS);
    bb.x = fmaf(bv.x - rmv.x, sc.x, bev.x);
    bb.y = fmaf(bv.y - rmv.y, sc.y, bev.y);
    bb.z = fmaf(bv.z - rmv.z, sc.z, bev.z);
    bb.w = fmaf(bv.w - rmv.w, sc.w, bev.w);

    #pragma unroll
    for (int s = 0; s < 4; s++) {
        float4 w = wv[s];
        w.x *= sc.x; w.y *= sc.y; w.z *= sc.z; w.w *= sc.w;
        ((float4*)Ws)[t + 256 * s] = w;
        ((float4*)zs)[t + 256 * s] = zst[s];
    }
    __syncthreads();

    float4 acc[4];
    gemm64(Ws, zs, rg, c4, acc);

    int row0 = R0 + rg * 4;
    #pragma unroll
    for (int r = 0; r < 4; r++) {
        int row = row0 + r;
        float4 hv = f4relu_add(acc[r], bb);
        if (row < NN) ((float4*)d_h)[row * HV + c4] = hv;
        if (do_pn) {
            int gg = (row < NN) ? __ldg(batch + row) : 0;
            if (row < NN) red_add4(&((float4*)d_gsum)[gg * HV + c4], hv);
            float v = (row < NN) ? (hv.x*hv.x + hv.y*hv.y + hv.z*hv.z + hv.w*hv.w) : 0.f;
            #pragma unroll
            for (int o = 1; o < 16; o <<= 1) v += __shfl_xor_sync(0xffffffffu, v, o);
            if (c4 == 0 && row < NN) atomicAdd(&d_gss[gg], v);
        }
    }
}

// ---------------- PairNorm per-graph mean & inverse denom; self-re-zeros ---
__global__ void meaninv_kernel() {
    int g = blockIdx.x, c = threadIdx.x;     // 64 threads
    float cnt = d_gcnt[g];
    float s = d_gsum[g * H + c];
    d_gsum[g * H + c] = 0.f;
    float mean = s / cnt;
    d_mean[g * H + c] = mean;
    float part = mean * s;
    #pragma unroll
    for (int o = 16; o; o >>= 1) part += __shfl_down_sync(0xffffffffu, part, o);
    __shared__ float red[2];
    if ((c & 31) == 0) red[c >> 5] = part;
    __syncthreads();
    if (c == 0) {
        float ss = d_gss[g];
        d_gss[g] = 0.f;
        float var = (ss - (red[0] + red[1])) / cnt;
        d_invd[g] = rsqrtf(PN_EPS + var);
    }
}

// ---------------- PairNorm apply -------------------------------------------
__global__ void __launch_bounds__(256) norm_kernel(const int* __restrict__ batch) {
    int idx = blockIdx.x * 256 + threadIdx.x;    // exactly NN*HV
    int row = idx >> 4, ln = idx & 15;
    int g = __ldg(batch + row);
    float4 hv = ((const float4*)d_h)[idx];
    float4 m = ((const float4*)d_mean)[g * HV + ln];
    float id = d_invd[g];
    hv.x = (hv.x - m.x) * id;
    hv.y = (hv.y - m.y) * id;
    hv.z = (hv.z - m.z) * id;
    hv.w = (hv.w - m.w) * id;
    ((float4*)d_h)[idx] = hv;
}

// ---------------- global add pool ------------------------------------------
__global__ void __launch_bounds__(256) pool_kernel(const int* __restrict__ batch) {
    int idx = blockIdx.x * 256 + threadIdx.x;    // NN*HV
    int row = idx >> 4, ln = idx & 15;
    int g = __ldg(batch + row);
    float4 hv = ((const float4*)d_h)[idx];
    red_add4(&((float4*)d_pool)[g * HV + ln], hv);
}

// ---------------- classifier; self-re-zeros pool ---------------------------
__global__ void cls_kernel(const float* __restrict__ W, const float* __restrict__ b,
                           float* __restrict__ out) {
    int g = blockIdx.x, c = threadIdx.x;     // 64 threads
    float p = d_pool[g * H + c];
    d_pool[g * H + c] = 0.f;
    float a = p * W[c * NOUT + 0];
    float bb = p * W[c * NOUT + 1];
    #pragma unroll
    for (int o = 16; o; o >>= 1) {
        a  += __shfl_down_sync(0xffffffffu, a, o);
        bb += __shfl_down_sync(0xffffffffu, bb, o);
    }
    __shared__ float sa[2], sb[2];
    if ((c & 31) == 0) { sa[c >> 5] = a; sb[c >> 5] = bb; }
    __syncthreads();
    if (c == 0) {
        out[g * NOUT + 0] = sa[0] + sa[1] + b[0];
        out[g * NOUT + 1] = sb[0] + sb[1] + b[1];
    }
}

// ---------------------------------------------------------------------------
extern "C" void kernel_launch(void* const* d_in, const int* in_sizes, int n_in,
                              void* d_out, int out_size) {
    const float* x        = (const float*)d_in[0];
    const int*   ei       = (const int*)  d_in[1];
    const float* eattr    = (const float*)d_in[2];
    const int*   batch    = (const int*)  d_in[3];
    const float* lin_W    = (const float*)d_in[4];
    const float* lin_b    = (const float*)d_in[5];
    const float* edge_W   = (const float*)d_in[6];
    const float* edge_b   = (const float*)d_in[7];
    const float* mlp_W1   = (const float*)d_in[8];
    const float* mlp_b1   = (const float*)d_in[9];
    const float* mbn_g    = (const float*)d_in[10];
    const float* mbn_b    = (const float*)d_in[11];
    const float* mbn_rm   = (const float*)d_in[12];
    const float* mbn_rv   = (const float*)d_in[13];
    const float* mlp_W2   = (const float*)d_in[14];
    const float* mlp_b2   = (const float*)d_in[15];
    const float* eps      = (const float*)d_in[16];
    const float* bn_g     = (const float*)d_in[17];
    const float* bn_b     = (const float*)d_in[18];
    const float* bn_rm    = (const float*)d_in[19];
    const float* bn_rv    = (const float*)d_in[20];
    const float* cls_W    = (const float*)d_in[21];
    const float* cls_b    = (const float*)d_in[22];
    float* out = (float*)d_out;

    count_kernel<<<2, 256>>>(batch);
    deg_kernel<<<NE / 256, 256>>>(ei);
    scan_kernel<<<1, SCAN_T>>>();
    scatter_kernel<<<NE / 256, 256>>>(ei, eattr);
    lin_in_kernel<<<NPAD / 16, 256>>>(x, lin_W, lin_b);

    for (int i = 0; i < NL; i++) {
        gine_agg_kernel<<<NPAD / 16, 256>>>(edge_W + i * EDIM * H, edge_b + i * H);
        int do_pn = (i < NL - 1) ? 1 : 0;
        mlp1_kernel<<<NPAD / 64, 256>>>(
            mlp_W1 + i * H * H, mlp_b1 + i * H,
            mbn_g + i * H, mbn_b + i * H, mbn_rm + i * H, mbn_rv + i * H,
            eps + i);
        mlp2_kernel<<<NPAD / 64, 256>>>(
            mlp_W2 + i * H * H, mlp_b2 + i * H,
            bn_g + i * H, bn_b + i * H, bn_rm + i * H, bn_rv + i * H,
            batch, do_pn);
        if (do_pn) {
            meaninv_kernel<<<NG, H>>>();
            norm_kernel<<<(NN * HV) / 256, 256>>>(batch);
        }
    }

    pool_kernel<<<(NN * HV) / 256, 256>>>(batch);
    cls_kernel<<<NG, H>>>(cls_W, cls_b, out);
}

// round 9
// speedup vs baseline: 1.1445x; 1.1445x over previous
#include <cuda_runtime.h>
#include <cuda_fp16.h>
#include <math.h>

#define NN    50000
#define NE    800000
#define INF_  32
#define H     64
#define HV    16      // H/4 (float4 lanes per row)
#define EDIM  4
#define NL    3
#define NG    512
#define NOUT  2
#define NPAD  50048   // 782 * 64 = 3128 * 16
#define BN_EPS 1e-5f
#define PN_EPS 1e-5f

// ---------------- persistent device scratch (zero-initialized at load) -----
__device__ float d_h[NPAD * H];
__device__ __align__(16) __half d_h16[NPAD * H];   // fp16 shadow for gathers
__device__ float d_agg[NPAD * H];
__device__ float d_tmp[NPAD * H];
__device__ float d_gsum[NG * H];
__device__ float d_gss[NG];
__device__ float d_gcnt[NG];
__device__ float d_mean[NG * H];
__device__ float d_invd[NG];
__device__ float d_pool[NG * H];

// 16-byte vector reduction to global (sm_90+)
__device__ __forceinline__ void red_add4(float4* a, float4 v) {
    asm volatile("red.global.add.v4.f32 [%0], {%1,%2,%3,%4};"
                 :: "l"(a), "f"(v.x), "f"(v.y), "f"(v.z), "f"(v.w) : "memory");
}

__device__ __forceinline__ float4 f4zero() { return make_float4(0.f, 0.f, 0.f, 0.f); }

__device__ __forceinline__ void f4fma(float4& acc, float s, const float4 w) {
    acc.x = fmaf(s, w.x, acc.x);
    acc.y = fmaf(s, w.y, acc.y);
    acc.z = fmaf(s, w.z, acc.z);
    acc.w = fmaf(s, w.w, acc.w);
}

__device__ __forceinline__ float4 f4relu_add(float4 a, float4 b) {
    return make_float4(fmaxf(a.x + b.x, 0.f), fmaxf(a.y + b.y, 0.f),
                       fmaxf(a.z + b.z, 0.f), fmaxf(a.w + b.w, 0.f));
}

__device__ __forceinline__ uint2 f4_to_h4(float4 v) {
    __half2 lo = __floats2half2_rn(v.x, v.y);
    __half2 hi = __floats2half2_rn(v.z, v.w);
    uint2 r;
    r.x = *reinterpret_cast<unsigned*>(&lo);
    r.y = *reinterpret_cast<unsigned*>(&hi);
    return r;
}

__device__ __forceinline__ float4 h4_to_f4(uint2 u) {
    __half2 lo = *reinterpret_cast<__half2*>(&u.x);
    __half2 hi = *reinterpret_cast<__half2*>(&u.y);
    float2 a = __half22float2(lo);
    float2 b = __half22float2(hi);
    return make_float4(a.x, a.y, b.x, b.y);
}

// 4x4 register-patch GEMM over 64x64 tile in smem.
__device__ __forceinline__ void gemm64(const float* __restrict__ Ws,
                                       const float* __restrict__ zs,
                                       int rg, int c4, float4 acc[4]) {
    acc[0] = f4zero(); acc[1] = f4zero(); acc[2] = f4zero(); acc[3] = f4zero();
    #pragma unroll
    for (int k4 = 0; k4 < 16; k4++) {
        float4 w0 = *(const float4*)&Ws[(k4 * 4 + 0) * H + c4 * 4];
        float4 w1 = *(const float4*)&Ws[(k4 * 4 + 1) * H + c4 * 4];
        float4 w2 = *(const float4*)&Ws[(k4 * 4 + 2) * H + c4 * 4];
        float4 w3 = *(const float4*)&Ws[(k4 * 4 + 3) * H + c4 * 4];
        float4 z0 = *(const float4*)&zs[(rg * 4 + 0) * H + k4 * 4];
        float4 z1 = *(const float4*)&zs[(rg * 4 + 1) * H + k4 * 4];
        float4 z2 = *(const float4*)&zs[(rg * 4 + 2) * H + k4 * 4];
        float4 z3 = *(const float4*)&zs[(rg * 4 + 3) * H + k4 * 4];
        f4fma(acc[0], z0.x, w0); f4fma(acc[0], z0.y, w1); f4fma(acc[0], z0.z, w2); f4fma(acc[0], z0.w, w3);
        f4fma(acc[1], z1.x, w0); f4fma(acc[1], z1.y, w1); f4fma(acc[1], z1.z, w2); f4fma(acc[1], z1.w, w3);
        f4fma(acc[2], z2.x, w0); f4fma(acc[2], z2.y, w1); f4fma(acc[2], z2.z, w2); f4fma(acc[2], z2.w, w3);
        f4fma(acc[3], z3.x, w0); f4fma(acc[3], z3.y, w1); f4fma(acc[3], z3.z, w2); f4fma(acc[3], z3.w, w3);
    }
}

// ---------------- counts: batch is sorted -> binary search per graph -------
__global__ void count_kernel(const int* __restrict__ batch) {
    int g = blockIdx.x * blockDim.x + threadIdx.x;
    if (g >= NG) return;
    int lo = 0, hi = NN;
    while (lo < hi) { int m = (lo + hi) >> 1; if (batch[m] < g) lo = m + 1; else hi = m; }
    int s = lo;
    lo = 0; hi = NN;
    while (lo < hi) { int m = (lo + hi) >> 1; if (batch[m] < g + 1) lo = m + 1; else hi = m; }
    d_gcnt[g] = fmaxf((float)(lo - s), 1.0f);
}

// ---------------- input linear: h = x @ W_in + b ; zeroes d_agg; h16 -------
__global__ void __launch_bounds__(256) lin_in_kernel(const float* __restrict__ x,
                                                     const float* __restrict__ W,
                                                     const float* __restrict__ b) {
    __shared__ __align__(16) float4 Ws[INF_ * HV];
    __shared__ __align__(16) float4 bs[HV];
    int t = threadIdx.x;
    for (int j = t; j < INF_ * HV; j += 256) Ws[j] = ((const float4*)W)[j];
    if (t < HV) bs[t] = ((const float4*)b)[t];
    __syncthreads();

    int lane = t & 15, rloc = t >> 4;
    int row = blockIdx.x * 16 + rloc;

    ((float4*)d_agg)[row * HV + lane] = f4zero();

    if (row < NN) {
        float4 acc = bs[lane];
        const float* xr = x + row * INF_;
        #pragma unroll
        for (int k = 0; k < INF_; k++) {
            float xv = __ldg(xr + k);
            f4fma(acc, xv, Ws[k * HV + lane]);
        }
        ((float4*)d_h)[row * HV + lane] = acc;
        ((uint2*)d_h16)[row * HV + lane] = f4_to_h4(acc);
    }
}

// ---------------- edge kernel: agg[dst] += relu(h16[src] + ea @ We + be) ---
__global__ void __launch_bounds__(256) edge_kernel(const int* __restrict__ ei,
                                                   const float* __restrict__ eattr,
                                                   const float* __restrict__ eW,
                                                   const float* __restrict__ eb) {
    __shared__ __align__(16) float4 Ws[EDIM * HV];
    __shared__ __align__(16) float4 bs[HV];
    int t = threadIdx.x;
    if (t < EDIM * HV) Ws[t] = ((const float4*)eW)[t];
    if (t < HV) bs[t] = ((const float4*)eb)[t];
    __syncthreads();

    int e    = blockIdx.x * 16 + (t >> 4);  // exactly NE = 50000*16 edges
    int lane = t & 15;
    int src = __ldg(ei + e);
    int dst = __ldg(ei + NE + e);
    float4 a = __ldg((const float4*)eattr + e);

    float4 v = bs[lane];
    f4fma(v, a.x, Ws[0 * HV + lane]);
    f4fma(v, a.y, Ws[1 * HV + lane]);
    f4fma(v, a.z, Ws[2 * HV + lane]);
    f4fma(v, a.w, Ws[3 * HV + lane]);

    uint2 hraw = __ldg((const uint2*)d_h16 + src * HV + lane);
    float4 hv = h4_to_f4(hraw);
    float4 m = f4relu_add(v, hv);
    red_add4((float4*)d_agg + dst * HV + lane, m);
}

// ---------------- MLP stage 1: d_tmp = relu(BN1(z @ W1 + b1)) --------------
__global__ void __launch_bounds__(256) mlp1_kernel(
    const float* __restrict__ W1, const float* __restrict__ b1,
    const float* __restrict__ g1, const float* __restrict__ be1,
    const float* __restrict__ rm1, const float* __restrict__ rv1,
    const float* __restrict__ epsp, int do_zero)
{
    __shared__ __align__(16) float Ws[H * H];
    __shared__ __align__(16) float zs[64 * H];

    int t = threadIdx.x;
    int c4 = t & 15, rg = t >> 4;
    int c0 = c4 * 4;
    int R0 = blockIdx.x * 64;

    float4 wv[4];
    #pragma unroll
    for (int s = 0; s < 4; s++) wv[s] = __ldg((const float4*)W1 + t + 256 * s);

    float4 gv  = __ldg((const float4*)(g1 + c0));
    float4 rvv = __ldg((const float4*)(rv1 + c0));
    float4 bv  = __ldg((const float4*)(b1 + c0));
    float4 bev = __ldg((const float4*)(be1 + c0));
    float4 rmv = __ldg((const float4*)(rm1 + c0));
    float epv = 1.0f + __ldg(epsp);

    float4 zst[4];
    #pragma unroll
    for (int s = 0; s < 4; s++) {
        int gi = R0 * HV + t + 256 * s;
        float4 hv = __ldg((const float4*)d_h + gi);
        float4 av = __ldg((const float4*)d_agg + gi);
        zst[s] = make_float4(fmaf(epv, hv.x, av.x), fmaf(epv, hv.y, av.y),
                             fmaf(epv, hv.z, av.z), fmaf(epv, hv.w, av.w));
        if (do_zero) ((float4*)d_agg)[gi] = f4zero();
    }

    float4 sc, bb;
    sc.x = gv.x * rsqrtf(rvv.x + BN_EPS);
    sc.y = gv.y * rsqrtf(rvv.y + BN_EPS);
    sc.z = gv.z * rsqrtf(rvv.z + BN_EPS);
    sc.w = gv.w * rsqrtf(rvv.w + BN_EPS);
    bb.x = fmaf(bv.x - rmv.x, sc.x, bev.x);
    bb.y = fmaf(bv.y - rmv.y, sc.y, bev.y);
    bb.z = fmaf(bv.z - rmv.z, sc.z, bev.z);
    bb.w = fmaf(bv.w - rmv.w, sc.w, bev.w);

    #pragma unroll
    for (int s = 0; s < 4; s++) {
        float4 w = wv[s];
        w.x *= sc.x; w.y *= sc.y; w.z *= sc.z; w.w *= sc.w;
        ((float4*)Ws)[t + 256 * s] = w;
        ((float4*)zs)[t + 256 * s] = zst[s];
    }
    __syncthreads();

    float4 acc[4];
    gemm64(Ws, zs, rg, c4, acc);

    int row0 = R0 + rg * 4;
    #pragma unroll
    for (int r = 0; r < 4; r++) {
        int row = row0 + r;
        if (row < NN) ((float4*)d_tmp)[row * HV + c4] = f4relu_add(acc[r], bb);
    }
}

// ---------------- MLP stage 2: d_h = relu(BN2(y @ W2 + b2)) ----------------
// do_pn=1: emit PairNorm stats. do_pn=0 (last layer): fuse global add pool.
__global__ void __launch_bounds__(256) mlp2_kernel(
    const float* __restrict__ W2, const float* __restrict__ b2,
    const float* __restrict__ g2, const float* __restrict__ be2,
    const float* __restrict__ rm2, const float* __restrict__ rv2,
    const int* __restrict__ batch, int do_pn)
{
    __shared__ __align__(16) float Ws[H * H];
    __shared__ __align__(16) float zs[64 * H];

    int t = threadIdx.x;
    int c4 = t & 15, rg = t >> 4;
    int c0 = c4 * 4;
    int R0 = blockIdx.x * 64;

    float4 wv[4];
    #pragma unroll
    for (int s = 0; s < 4; s++) wv[s] = __ldg((const float4*)W2 + t + 256 * s);

    float4 gv  = __ldg((const float4*)(g2 + c0));
    float4 rvv = __ldg((const float4*)(rv2 + c0));
    float4 bv  = __ldg((const float4*)(b2 + c0));
    float4 bev = __ldg((const float4*)(be2 + c0));
    float4 rmv = __ldg((const float4*)(rm2 + c0));

    float4 zst[4];
    #pragma unroll
    for (int s = 0; s < 4; s++)
        zst[s] = __ldg((const float4*)d_tmp + R0 * HV + t + 256 * s);

    float4 sc, bb;
    sc.x = gv.x * rsqrtf(rvv.x + BN_EPS);
    sc.y = gv.y * rsqrtf(rvv.y + BN_EPS);
    sc.z = gv.z * rsqrtf(rvv.z + BN_EPS);
    sc.w = gv.w * rsqrtf(rvv.w + BN_EPS);
    bb.x = fmaf(bv.x - rmv.x, sc.x, bev.x);
    bb.y = fmaf(bv.y - rmv.y, sc.y, bev.y);
    bb.z = fmaf(bv.z - rmv.z, sc.z, bev.z);
    bb.w = fmaf(bv.w - rmv.w, sc.w, bev.w);

    #pragma unroll
    for (int s = 0; s < 4; s++) {
        float4 w = wv[s];
        w.x *= sc.x; w.y *= sc.y; w.z *= sc.z; w.w *= sc.w;
        ((float4*)Ws)[t + 256 * s] = w;
        ((float4*)zs)[t + 256 * s] = zst[s];
    }
    __syncthreads();

    float4 acc[4];
    gemm64(Ws, zs, rg, c4, acc);

    int row0 = R0 + rg * 4;
    #pragma unroll
    for (int r = 0; r < 4; r++) {
        int row = row0 + r;
        float4 hv = f4relu_add(acc[r], bb);
        if (row < NN) ((float4*)d_h)[row * HV + c4] = hv;
        int gg = (row < NN) ? __ldg(batch + row) : 0;
        if (do_pn) {
            if (row < NN) red_add4(&((float4*)d_gsum)[gg * HV + c4], hv);
            float v = (row < NN) ? (hv.x*hv.x + hv.y*hv.y + hv.z*hv.z + hv.w*hv.w) : 0.f;
            #pragma unroll
            for (int o = 1; o < 16; o <<= 1) v += __shfl_xor_sync(0xffffffffu, v, o);
            if (c4 == 0 && row < NN) atomicAdd(&d_gss[gg], v);
        } else {
            // last layer: fused global add pool
            if (row < NN) red_add4(&((float4*)d_pool)[gg * HV + c4], hv);
        }
    }
}

// ---------------- PairNorm per-graph mean & inverse denom; self-re-zeros ---
__global__ void meaninv_kernel() {
    int g = blockIdx.x, c = threadIdx.x;     // 64 threads
    float cnt = d_gcnt[g];
    float s = d_gsum[g * H + c];
    d_gsum[g * H + c] = 0.f;
    float mean = s / cnt;
    d_mean[g * H + c] = mean;
    float part = mean * s;
    #pragma unroll
    for (int o = 16; o; o >>= 1) part += __shfl_down_sync(0xffffffffu, part, o);
    __shared__ float red[2];
    if ((c & 31) == 0) red[c >> 5] = part;
    __syncthreads();
    if (c == 0) {
        float ss = d_gss[g];
        d_gss[g] = 0.f;
        float var = (ss - (red[0] + red[1])) / cnt;
        d_invd[g] = rsqrtf(PN_EPS + var);
    }
}

// ---------------- PairNorm apply (also writes fp16 shadow) -----------------
__global__ void __launch_bounds__(256) norm_kernel(const int* __restrict__ batch) {
    int idx = blockIdx.x * 256 + threadIdx.x;    // exactly NN*HV
    int row = idx >> 4, ln = idx & 15;
    int g = __ldg(batch + row);
    float4 hv = ((const float4*)d_h)[idx];
    float4 m = ((const float4*)d_mean)[g * HV + ln];
    float id = d_invd[g];
    hv.x = (hv.x - m.x) * id;
    hv.y = (hv.y - m.y) * id;
    hv.z = (hv.z - m.z) * id;
    hv.w = (hv.w - m.w) * id;
    ((float4*)d_h)[idx] = hv;
    ((uint2*)d_h16)[idx] = f4_to_h4(hv);
}

// ---------------- classifier; self-re-zeros pool ---------------------------
__global__ void cls_kernel(const float* __restrict__ W, const float* __restrict__ b,
                           float* __restrict__ out) {
    int g = blockIdx.x, c = threadIdx.x;     // 64 threads
    float p = d_pool[g * H + c];
    d_pool[g * H + c] = 0.f;
    float a = p * W[c * NOUT + 0];
    float bb = p * W[c * NOUT + 1];
    #pragma unroll
    for (int o = 16; o; o >>= 1) {
        a  += __shfl_down_sync(0xffffffffu, a, o);
        bb += __shfl_down_sync(0xffffffffu, bb, o);
    }
    __shared__ float sa[2], sb[2];
    if ((c & 31) == 0) { sa[c >> 5] = a; sb[c >> 5] = bb; }
    __syncthreads();
    if (c == 0) {
        out[g * NOUT + 0] = sa[0] + sa[1] + b[0];
        out[g * NOUT + 1] = sb[0] + sb[1] + b[1];
    }
}

// ---------------------------------------------------------------------------
extern "C" void kernel_launch(void* const* d_in, const int* in_sizes, int n_in,
                              void* d_out, int out_size) {
    const float* x        = (const float*)d_in[0];
    const int*   ei       = (const int*)  d_in[1];
    const float* eattr    = (const float*)d_in[2];
    const int*   batch    = (const int*)  d_in[3];
    const float* lin_W    = (const float*)d_in[4];
    const float* lin_b    = (const float*)d_in[5];
    const float* edge_W   = (const float*)d_in[6];
    const float* edge_b   = (const float*)d_in[7];
    const float* mlp_W1   = (const float*)d_in[8];
    const float* mlp_b1   = (const float*)d_in[9];
    const float* mbn_g    = (const float*)d_in[10];
    const float* mbn_b    = (const float*)d_in[11];
    const float* mbn_rm   = (const float*)d_in[12];
    const float* mbn_rv   = (const float*)d_in[13];
    const float* mlp_W2   = (const float*)d_in[14];
    const float* mlp_b2   = (const float*)d_in[15];
    const float* eps      = (const float*)d_in[16];
    const float* bn_g     = (const float*)d_in[17];
    const float* bn_b     = (const float*)d_in[18];
    const float* bn_rm    = (const float*)d_in[19];
    const float* bn_rv    = (const float*)d_in[20];
    const float* cls_W    = (const float*)d_in[21];
    const float* cls_b    = (const float*)d_in[22];
    float* out = (float*)d_out;

    count_kernel<<<2, 256>>>(batch);
    lin_in_kernel<<<NPAD / 16, 256>>>(x, lin_W, lin_b);

    for (int i = 0; i < NL; i++) {
        edge_kernel<<<NE / 16, 256>>>(ei, eattr, edge_W + i * EDIM * H, edge_b + i * H);
        int do_pn = (i < NL - 1) ? 1 : 0;
        mlp1_kernel<<<NPAD / 64, 256>>>(
            mlp_W1 + i * H * H, mlp_b1 + i * H,
            mbn_g + i * H, mbn_b + i * H, mbn_rm + i * H, mbn_rv + i * H,
            eps + i, do_pn);
        mlp2_kernel<<<NPAD / 64, 256>>>(
            mlp_W2 + i * H * H, mlp_b2 + i * H,
            bn_g + i * H, bn_b + i * H, bn_rm + i * H, bn_rv + i * H,
            batch, do_pn);
        if (do_pn) {
            meaninv_kernel<<<NG, H>>>();
            norm_kernel<<<(NN * HV) / 256, 256>>>(batch);
        }
    }

    cls_kernel<<<NG, H>>>(cls_W, cls_b, out);
}

// round 11
// speedup vs baseline: 1.3599x; 1.1882x over previous
#include <cuda_runtime.h>
#include <cuda_fp16.h>
#include <math.h>

#define NN    50000
#define NE    800000
#define INF_  32
#define H     64
#define HV    16      // H/4 (float4 lanes per row)
#define EDIM  4
#define NL    3
#define NG    512
#define NOUT  2
#define NPAD  50048   // 782 * 64 = 3128 * 16
#define BN_EPS 1e-5f
#define PN_EPS 1e-5f
#define EPB   64      // edges per block in edge_kernel (4 per 16-thread group)

// ---------------- persistent device scratch (zero-initialized at load) -----
__device__ float d_h[NPAD * H];
__device__ __align__(16) __half d_h16[NPAD * H];   // fp16 shadow for gathers
__device__ float d_agg[NPAD * H];
__device__ float d_tmp[NPAD * H];
__device__ float d_gsum[NG * H];
__device__ float d_gss[NG];
__device__ float d_gcnt[NG];
__device__ float d_mean[NG * H];
__device__ float d_invd[NG];
__device__ float d_pool[NG * H];

// 16-byte vector reduction to global (sm_90+)
__device__ __forceinline__ void red_add4(float4* a, float4 v) {
    asm volatile("red.global.add.v4.f32 [%0], {%1,%2,%3,%4};"
                 :: "l"(a), "f"(v.x), "f"(v.y), "f"(v.z), "f"(v.w) : "memory");
}

__device__ __forceinline__ float4 f4zero() { return make_float4(0.f, 0.f, 0.f, 0.f); }

__device__ __forceinline__ void f4fma(float4& acc, float s, const float4 w) {
    acc.x = fmaf(s, w.x, acc.x);
    acc.y = fmaf(s, w.y, acc.y);
    acc.z = fmaf(s, w.z, acc.z);
    acc.w = fmaf(s, w.w, acc.w);
}

__device__ __forceinline__ float4 f4relu_add(float4 a, float4 b) {
    return make_float4(fmaxf(a.x + b.x, 0.f), fmaxf(a.y + b.y, 0.f),
                       fmaxf(a.z + b.z, 0.f), fmaxf(a.w + b.w, 0.f));
}

__device__ __forceinline__ uint2 f4_to_h4(float4 v) {
    __half2 lo = __floats2half2_rn(v.x, v.y);
    __half2 hi = __floats2half2_rn(v.z, v.w);
    uint2 r;
    r.x = *reinterpret_cast<unsigned*>(&lo);
    r.y = *reinterpret_cast<unsigned*>(&hi);
    return r;
}

__device__ __forceinline__ float4 h4_to_f4(uint2 u) {
    __half2 lo = *reinterpret_cast<__half2*>(&u.x);
    __half2 hi = *reinterpret_cast<__half2*>(&u.y);
    float2 a = __half22float2(lo);
    float2 b = __half22float2(hi);
    return make_float4(a.x, a.y, b.x, b.y);
}

// 4x4 register-patch GEMM over 64x64 tile in smem.
__device__ __forceinline__ void gemm64(const float* __restrict__ Ws,
                                       const float* __restrict__ zs,
                                       int rg, int c4, float4 acc[4]) {
    acc[0] = f4zero(); acc[1] = f4zero(); acc[2] = f4zero(); acc[3] = f4zero();
    #pragma unroll
    for (int k4 = 0; k4 < 16; k4++) {
        float4 w0 = *(const float4*)&Ws[(k4 * 4 + 0) * H + c4 * 4];
        float4 w1 = *(const float4*)&Ws[(k4 * 4 + 1) * H + c4 * 4];
        float4 w2 = *(const float4*)&Ws[(k4 * 4 + 2) * H + c4 * 4];
        float4 w3 = *(const float4*)&Ws[(k4 * 4 + 3) * H + c4 * 4];
        float4 z0 = *(const float4*)&zs[(rg * 4 + 0) * H + k4 * 4];
        float4 z1 = *(const float4*)&zs[(rg * 4 + 1) * H + k4 * 4];
        float4 z2 = *(const float4*)&zs[(rg * 4 + 2) * H + k4 * 4];
        float4 z3 = *(const float4*)&zs[(rg * 4 + 3) * H + k4 * 4];
        f4fma(acc[0], z0.x, w0); f4fma(acc[0], z0.y, w1); f4fma(acc[0], z0.z, w2); f4fma(acc[0], z0.w, w3);
        f4fma(acc[1], z1.x, w0); f4fma(acc[1], z1.y, w1); f4fma(acc[1], z1.z, w2); f4fma(acc[1], z1.w, w3);
        f4fma(acc[2], z2.x, w0); f4fma(acc[2], z2.y, w1); f4fma(acc[2], z2.z, w2); f4fma(acc[2], z2.w, w3);
        f4fma(acc[3], z3.x, w0); f4fma(acc[3], z3.y, w1); f4fma(acc[3], z3.z, w2); f4fma(acc[3], z3.w, w3);
    }
}

// ---------------- counts: batch is sorted -> binary search per graph -------
__global__ void count_kernel(const int* __restrict__ batch) {
    int g = blockIdx.x * blockDim.x + threadIdx.x;
    if (g >= NG) return;
    int lo = 0, hi = NN;
    while (lo < hi) { int m = (lo + hi) >> 1; if (batch[m] < g) lo = m + 1; else hi = m; }
    int s = lo;
    lo = 0; hi = NN;
    while (lo < hi) { int m = (lo + hi) >> 1; if (batch[m] < g + 1) lo = m + 1; else hi = m; }
    d_gcnt[g] = fmaxf((float)(lo - s), 1.0f);
}

// ---------------- input linear: h = x @ W_in + b ; zeroes d_agg; h16 -------
__global__ void __launch_bounds__(256) lin_in_kernel(const float* __restrict__ x,
                                                     const float* __restrict__ W,
                                                     const float* __restrict__ b) {
    __shared__ __align__(16) float4 Ws[INF_ * HV];
    __shared__ __align__(16) float4 bs[HV];
    int t = threadIdx.x;
    for (int j = t; j < INF_ * HV; j += 256) Ws[j] = ((const float4*)W)[j];
    if (t < HV) bs[t] = ((const float4*)b)[t];
    __syncthreads();

    int lane = t & 15, rloc = t >> 4;
    int row = blockIdx.x * 16 + rloc;

    ((float4*)d_agg)[row * HV + lane] = f4zero();

    if (row < NN) {
        float4 acc = bs[lane];
        const float* xr = x + row * INF_;
        #pragma unroll
        for (int k = 0; k < INF_; k++) {
            float xv = __ldg(xr + k);
            f4fma(acc, xv, Ws[k * HV + lane]);
        }
        ((float4*)d_h)[row * HV + lane] = acc;
        ((uint2*)d_h16)[row * HV + lane] = f4_to_h4(acc);
    }
}

// ---------------- edge kernel: agg[dst] += relu(h16[src] + ea @ We + be) ---
// 64 edges/block, 4 per 16-thread group; vectorized int4 index loads;
// all 4 gathers issued back-to-back for MLP.
__global__ void __launch_bounds__(256) edge_kernel(const int* __restrict__ ei,
                                                   const float* __restrict__ eattr,
                                                   const float* __restrict__ eW,
                                                   const float* __restrict__ eb) {
    __shared__ __align__(16) float4 Ws[EDIM * HV];
    __shared__ __align__(16) float4 bs[HV];
    int t = threadIdx.x;
    if (t < EDIM * HV) Ws[t] = ((const float4*)eW)[t];
    if (t < HV) bs[t] = ((const float4*)eb)[t];
    __syncthreads();

    int e0   = blockIdx.x * EPB + (t >> 4) * 4;   // first of 4 consecutive edges
    int lane = t & 15;

    int4 s4 = __ldg((const int4*)(ei) + (e0 >> 2));
    int4 t4 = __ldg((const int4*)(ei + NE) + (e0 >> 2));
    int src[4] = {s4.x, s4.y, s4.z, s4.w};
    int dst[4] = {t4.x, t4.y, t4.z, t4.w};

    float4 a[4];
    #pragma unroll
    for (int j = 0; j < 4; j++) a[j] = __ldg((const float4*)eattr + e0 + j);

    uint2 hr[4];
    #pragma unroll
    for (int j = 0; j < 4; j++)
        hr[j] = __ldg((const uint2*)d_h16 + src[j] * HV + lane);

    float4 w0 = Ws[0 * HV + lane], w1 = Ws[1 * HV + lane];
    float4 w2 = Ws[2 * HV + lane], w3 = Ws[3 * HV + lane];
    float4 bv = bs[lane];

    #pragma unroll
    for (int j = 0; j < 4; j++) {
        float4 v = bv;
        f4fma(v, a[j].x, w0);
        f4fma(v, a[j].y, w1);
        f4fma(v, a[j].z, w2);
        f4fma(v, a[j].w, w3);
        float4 m = f4relu_add(v, h4_to_f4(hr[j]));
        red_add4((float4*)d_agg + dst[j] * HV + lane, m);
    }
}

// ---------------- MLP stage 1: d_tmp = relu(BN1(z @ W1 + b1)) --------------
__global__ void __launch_bounds__(256) mlp1_kernel(
    const float* __restrict__ W1, const float* __restrict__ b1,
    const float* __restrict__ g1, const float* __restrict__ be1,
    const float* __restrict__ rm1, const float* __restrict__ rv1,
    const float* __restrict__ epsp, int do_zero)
{
    __shared__ __align__(16) float Ws[H * H];
    __shared__ __align__(16) float zs[64 * H];

    int t = threadIdx.x;
    int c4 = t & 15, rg = t >> 4;
    int c0 = c4 * 4;
    int R0 = blockIdx.x * 64;

    float4 wv[4];
    #pragma unroll
    for (int s = 0; s < 4; s++) wv[s] = __ldg((const float4*)W1 + t + 256 * s);

    float4 gv  = __ldg((const float4*)(g1 + c0));
    float4 rvv = __ldg((const float4*)(rv1 + c0));
    float4 bv  = __ldg((const float4*)(b1 + c0));
    float4 bev = __ldg((const float4*)(be1 + c0));
    float4 rmv = __ldg((const float4*)(rm1 + c0));
    float epv = 1.0f + __ldg(epsp);

    float4 zst[4];
    #pragma unroll
    for (int s = 0; s < 4; s++) {
        int gi = R0 * HV + t + 256 * s;
        float4 hv = __ldg((const float4*)d_h + gi);
        float4 av = __ldg((const float4*)d_agg + gi);
        zst[s] = make_float4(fmaf(epv, hv.x, av.x), fmaf(epv, hv.y, av.y),
                             fmaf(epv, hv.z, av.z), fmaf(epv, hv.w, av.w));
        if (do_zero) ((float4*)d_agg)[gi] = f4zero();
    }

    float4 sc, bb;
    sc.x = gv.x * rsqrtf(rvv.x + BN_EPS);
    sc.y = gv.y * rsqrtf(rvv.y + BN_EPS);
    sc.z = gv.z * rsqrtf(rvv.z + BN_EPS);
    sc.w = gv.w * rsqrtf(rvv.w + BN_EPS);
    bb.x = fmaf(bv.x - rmv.x, sc.x, bev.x);
    bb.y = fmaf(bv.y - rmv.y, sc.y, bev.y);
    bb.z = fmaf(bv.z - rmv.z, sc.z, bev.z);
    bb.w = fmaf(bv.w - rmv.w, sc.w, bev.w);

    #pragma unroll
    for (int s = 0; s < 4; s++) {
        float4 w = wv[s];
        w.x *= sc.x; w.y *= sc.y; w.z *= sc.z; w.w *= sc.w;
        ((float4*)Ws)[t + 256 * s] = w;
        ((float4*)zs)[t + 256 * s] = zst[s];
    }
    __syncthreads();

    float4 acc[4];
    gemm64(Ws, zs, rg, c4, acc);

    int row0 = R0 + rg * 4;
    #pragma unroll
    for (int r = 0; r < 4; r++) {
        int row = row0 + r;
        if (row < NN) ((float4*)d_tmp)[row * HV + c4] = f4relu_add(acc[r], bb);
    }
}

// ---------------- MLP stage 2: d_h = relu(BN2(y @ W2 + b2)) ----------------
// do_pn=1: emit PairNorm stats. do_pn=0 (last layer): fuse global add pool.
__global__ void __launch_bounds__(256) mlp2_kernel(
    const float* __restrict__ W2, const float* __restrict__ b2,
    const float* __restrict__ g2, const float* __restrict__ be2,
    const float* __restrict__ rm2, const float* __restrict__ rv2,
    const int* __restrict__ batch, int do_pn)
{
    __shared__ __align__(16) float Ws[H * H];
    __shared__ __align__(16) float zs[64 * H];

    int t = threadIdx.x;
    int c4 = t & 15, rg = t >> 4;
    int c0 = c4 * 4;
    int R0 = blockIdx.x * 64;

    float4 wv[4];
    #pragma unroll
    for (int s = 0; s < 4; s++) wv[s] = __ldg((const float4*)W2 + t + 256 * s);

    float4 gv  = __ldg((const float4*)(g2 + c0));
    float4 rvv = __ldg((const float4*)(rv2 + c0));
    float4 bv  = __ldg((const float4*)(b2 + c0));
    float4 bev = __ldg((const float4*)(be2 + c0));
    float4 rmv = __ldg((const float4*)(rm2 + c0));

    float4 zst[4];
    #pragma unroll
    for (int s = 0; s < 4; s++)
        zst[s] = __ldg((const float4*)d_tmp + R0 * HV + t + 256 * s);

    float4 sc, bb;
    sc.x = gv.x * rsqrtf(rvv.x + BN_EPS);
    sc.y = gv.y * rsqrtf(rvv.y + BN_EPS);
    sc.z = gv.z * rsqrtf(rvv.z + BN_EPS);
    sc.w = gv.w * rsqrtf(rvv.w + BN_EPS);
    bb.x = fmaf(bv.x - rmv.x, sc.x, bev.x);
    bb.y = fmaf(bv.y - rmv.y, sc.y, bev.y);
    bb.z = fmaf(bv.z - rmv.z, sc.z, bev.z);
    bb.w = fmaf(bv.w - rmv.w, sc.w, bev.w);

    #pragma unroll
    for (int s = 0; s < 4; s++) {
        float4 w = wv[s];
        w.x *= sc.x; w.y *= sc.y; w.z *= sc.z; w.w *= sc.w;
        ((float4*)Ws)[t + 256 * s] = w;
        ((float4*)zs)[t + 256 * s] = zst[s];
    }
    __syncthreads();

    float4 acc[4];
    gemm64(Ws, zs, rg, c4, acc);

    int row0 = R0 + rg * 4;
    #pragma unroll
    for (int r = 0; r < 4; r++) {
        int row = row0 + r;
        float4 hv = f4relu_add(acc[r], bb);
        if (row < NN) ((float4*)d_h)[row * HV + c4] = hv;
        int gg = (row < NN) ? __ldg(batch + row) : 0;
        if (do_pn) {
            if (row < NN) red_add4(&((float4*)d_gsum)[gg * HV + c4], hv);
            float v = (row < NN) ? (hv.x*hv.x + hv.y*hv.y + hv.z*hv.z + hv.w*hv.w) : 0.f;
            #pragma unroll
            for (int o = 1; o < 16; o <<= 1) v += __shfl_xor_sync(0xffffffffu, v, o);
            if (c4 == 0 && row < NN) atomicAdd(&d_gss[gg], v);
        } else {
            // last layer: fused global add pool
            if (row < NN) red_add4(&((float4*)d_pool)[gg * HV + c4], hv);
        }
    }
}

// ---------------- PairNorm per-graph mean & inverse denom; self-re-zeros ---
__global__ void meaninv_kernel() {
    int g = blockIdx.x, c = threadIdx.x;     // 64 threads
    float cnt = d_gcnt[g];
    float s = d_gsum[g * H + c];
    d_gsum[g * H + c] = 0.f;
    float mean = s / cnt;
    d_mean[g * H + c] = mean;
    float part = mean * s;
    #pragma unroll
    for (int o = 16; o; o >>= 1) part += __shfl_down_sync(0xffffffffu, part, o);
    __shared__ float red[2];
    if ((c & 31) == 0) red[c >> 5] = part;
    __syncthreads();
    if (c == 0) {
        float ss = d_gss[g];
        d_gss[g] = 0.f;
        float var = (ss - (red[0] + red[1])) / cnt;
        d_invd[g] = rsqrtf(PN_EPS + var);
    }
}

// ---------------- PairNorm apply (also writes fp16 shadow) -----------------
__global__ void __launch_bounds__(256) norm_kernel(const int* __restrict__ batch) {
    int idx = blockIdx.x * 256 + threadIdx.x;    // exactly NN*HV
    int row = idx >> 4, ln = idx & 15;
    int g = __ldg(batch + row);
    float4 hv = ((const float4*)d_h)[idx];
    float4 m = ((const float4*)d_mean)[g * HV + ln];
    float id = d_invd[g];
    hv.x = (hv.x - m.x) * id;
    hv.y = (hv.y - m.y) * id;
    hv.z = (hv.z - m.z) * id;
    hv.w = (hv.w - m.w) * id;
    ((float4*)d_h)[idx] = hv;
    ((uint2*)d_h16)[idx] = f4_to_h4(hv);
}

// ---------------- classifier; self-re-zeros pool ---------------------------
__global__ void cls_kernel(const float* __restrict__ W, const float* __restrict__ b,
                           float* __restrict__ out) {
    int g = blockIdx.x, c = threadIdx.x;     // 64 threads
    float p = d_pool[g * H + c];
    d_pool[g * H + c] = 0.f;
    float a = p * W[c * NOUT + 0];
    float bb = p * W[c * NOUT + 1];
    #pragma unroll
    for (int o = 16; o; o >>= 1) {
        a  += __shfl_down_sync(0xffffffffu, a, o);
        bb += __shfl_down_sync(0xffffffffu, bb, o);
    }
    __shared__ float sa[2], sb[2];
    if ((c & 31) == 0) { sa[c >> 5] = a; sb[c >> 5] = bb; }
    __syncthreads();
    if (c == 0) {
        out[g * NOUT + 0] = sa[0] + sa[1] + b[0];
        out[g * NOUT + 1] = sb[0] + sb[1] + b[1];
    }
}

// ---------------------------------------------------------------------------
extern "C" void kernel_launch(void* const* d_in, const int* in_sizes, int n_in,
                              void* d_out, int out_size) {
    const float* x        = (const float*)d_in[0];
    const int*   ei       = (const int*)  d_in[1];
    const float* eattr    = (const float*)d_in[2];
    const int*   batch    = (const int*)  d_in[3];
    const float* lin_W    = (const float*)d_in[4];
    const float* lin_b    = (const float*)d_in[5];
    const float* edge_W   = (const float*)d_in[6];
    const float* edge_b   = (const float*)d_in[7];
    const float* mlp_W1   = (const float*)d_in[8];
    const float* mlp_b1   = (const float*)d_in[9];
    const float* mbn_g    = (const float*)d_in[10];
    const float* mbn_b    = (const float*)d_in[11];
    const float* mbn_rm   = (const float*)d_in[12];
    const float* mbn_rv   = (const float*)d_in[13];
    const float* mlp_W2   = (const float*)d_in[14];
    const float* mlp_b2   = (const float*)d_in[15];
    const float* eps      = (const float*)d_in[16];
    const float* bn_g     = (const float*)d_in[17];
    const float* bn_b     = (const float*)d_in[18];
    const float* bn_rm    = (const float*)d_in[19];
    const float* bn_rv    = (const float*)d_in[20];
    const float* cls_W    = (const float*)d_in[21];
    const float* cls_b    = (const float*)d_in[22];
    float* out = (float*)d_out;

    count_kernel<<<2, 256>>>(batch);
    lin_in_kernel<<<NPAD / 16, 256>>>(x, lin_W, lin_b);

    for (int i = 0; i < NL; i++) {
        edge_kernel<<<NE / EPB, 256>>>(ei, eattr, edge_W + i * EDIM * H, edge_b + i * H);
        int do_pn = (i < NL - 1) ? 1 : 0;
        mlp1_kernel<<<NPAD / 64, 256>>>(
            mlp_W1 + i * H * H, mlp_b1 + i * H,
            mbn_g + i * H, mbn_b + i * H, mbn_rm + i * H, mbn_rv + i * H,
            eps + i, do_pn);
        mlp2_kernel<<<NPAD / 64, 256>>>(
            mlp_W2 + i * H * H, mlp_b2 + i * H,
            bn_g + i * H, bn_b + i * H, bn_rm + i * H, bn_rv + i * H,
            batch, do_pn);
        if (do_pn) {
            meaninv_kernel<<<NG, H>>>();
            norm_kernel<<<(NN * HV) / 256, 256>>>(batch);
        }
    }

    cls_kernel<<<NG, H>>>(cls_W, cls_b, out);
}

// round 12
// speedup vs baseline: 1.4506x; 1.0666x over previous
#include <cuda_runtime.h>
#include <cuda_fp16.h>
#include <math.h>

#define NN    50000
#define NE    800000
#define INF_  32
#define H     64
#define HV    16      // H/4 (float4 lanes per row)
#define EDIM  4
#define NL    3
#define NG    512
#define NOUT  2
#define NPAD  50048   // 782 * 64 = 3128 * 16
#define BN_EPS 1e-5f
#define PN_EPS 1e-5f
#define EPB   128     // edges per block in edge_kernel (8 per 16-thread group)

// ---------------- persistent device scratch (zero-initialized at load) -----
__device__ float d_h[NPAD * H];
__device__ __align__(16) __half d_h16[NPAD * H];   // fp16 shadow for gathers
__device__ float d_agg[NPAD * H];
__device__ float d_gsum[NG * H];
__device__ float d_gss[NG];
__device__ float d_gcnt[NG];
__device__ float d_mean[NG * H];
__device__ float d_invd[NG];
__device__ float d_pool[NG * H];

// 16-byte vector reduction to global (sm_90+)
__device__ __forceinline__ void red_add4(float4* a, float4 v) {
    asm volatile("red.global.add.v4.f32 [%0], {%1,%2,%3,%4};"
                 :: "l"(a), "f"(v.x), "f"(v.y), "f"(v.z), "f"(v.w) : "memory");
}

__device__ __forceinline__ float4 f4zero() { return make_float4(0.f, 0.f, 0.f, 0.f); }

__device__ __forceinline__ void f4fma(float4& acc, float s, const float4 w) {
    acc.x = fmaf(s, w.x, acc.x);
    acc.y = fmaf(s, w.y, acc.y);
    acc.z = fmaf(s, w.z, acc.z);
    acc.w = fmaf(s, w.w, acc.w);
}

__device__ __forceinline__ float4 f4relu_add(float4 a, float4 b) {
    return make_float4(fmaxf(a.x + b.x, 0.f), fmaxf(a.y + b.y, 0.f),
                       fmaxf(a.z + b.z, 0.f), fmaxf(a.w + b.w, 0.f));
}

__device__ __forceinline__ uint2 f4_to_h4(float4 v) {
    __half2 lo = __floats2half2_rn(v.x, v.y);
    __half2 hi = __floats2half2_rn(v.z, v.w);
    uint2 r;
    r.x = *reinterpret_cast<unsigned*>(&lo);
    r.y = *reinterpret_cast<unsigned*>(&hi);
    return r;
}

__device__ __forceinline__ float4 h4_to_f4(uint2 u) {
    __half2 lo = *reinterpret_cast<__half2*>(&u.x);
    __half2 hi = *reinterpret_cast<__half2*>(&u.y);
    float2 a = __half22float2(lo);
    float2 b = __half22float2(hi);
    return make_float4(a.x, a.y, b.x, b.y);
}

// 4x4 register-patch GEMM over 64x64 tile in smem.
__device__ __forceinline__ void gemm64(const float* __restrict__ Ws,
                                       const float* __restrict__ zs,
                                       int rg, int c4, float4 acc[4]) {
    acc[0] = f4zero(); acc[1] = f4zero(); acc[2] = f4zero(); acc[3] = f4zero();
    #pragma unroll
    for (int k4 = 0; k4 < 16; k4++) {
        float4 w0 = *(const float4*)&Ws[(k4 * 4 + 0) * H + c4 * 4];
        float4 w1 = *(const float4*)&Ws[(k4 * 4 + 1) * H + c4 * 4];
        float4 w2 = *(const float4*)&Ws[(k4 * 4 + 2) * H + c4 * 4];
        float4 w3 = *(const float4*)&Ws[(k4 * 4 + 3) * H + c4 * 4];
        float4 z0 = *(const float4*)&zs[(rg * 4 + 0) * H + k4 * 4];
        float4 z1 = *(const float4*)&zs[(rg * 4 + 1) * H + k4 * 4];
        float4 z2 = *(const float4*)&zs[(rg * 4 + 2) * H + k4 * 4];
        float4 z3 = *(const float4*)&zs[(rg * 4 + 3) * H + k4 * 4];
        f4fma(acc[0], z0.x, w0); f4fma(acc[0], z0.y, w1); f4fma(acc[0], z0.z, w2); f4fma(acc[0], z0.w, w3);
        f4fma(acc[1], z1.x, w0); f4fma(acc[1], z1.y, w1); f4fma(acc[1], z1.z, w2); f4fma(acc[1], z1.w, w3);
        f4fma(acc[2], z2.x, w0); f4fma(acc[2], z2.y, w1); f4fma(acc[2], z2.z, w2); f4fma(acc[2], z2.w, w3);
        f4fma(acc[3], z3.x, w0); f4fma(acc[3], z3.y, w1); f4fma(acc[3], z3.z, w2); f4fma(acc[3], z3.w, w3);
    }
}

// ---------------- counts: batch is sorted -> binary search per graph -------
__global__ void count_kernel(const int* __restrict__ batch) {
    int g = blockIdx.x * blockDim.x + threadIdx.x;
    if (g >= NG) return;
    int lo = 0, hi = NN;
    while (lo < hi) { int m = (lo + hi) >> 1; if (batch[m] < g) lo = m + 1; else hi = m; }
    int s = lo;
    lo = 0; hi = NN;
    while (lo < hi) { int m = (lo + hi) >> 1; if (batch[m] < g + 1) lo = m + 1; else hi = m; }
    d_gcnt[g] = fmaxf((float)(lo - s), 1.0f);
}

// ---------------- input linear: h = x @ W_in + b ; zeroes d_agg; h16 -------
__global__ void __launch_bounds__(256) lin_in_kernel(const float* __restrict__ x,
                                                     const float* __restrict__ W,
                                                     const float* __restrict__ b) {
    __shared__ __align__(16) float4 Ws[INF_ * HV];
    __shared__ __align__(16) float4 bs[HV];
    int t = threadIdx.x;
    for (int j = t; j < INF_ * HV; j += 256) Ws[j] = ((const float4*)W)[j];
    if (t < HV) bs[t] = ((const float4*)b)[t];
    __syncthreads();

    int lane = t & 15, rloc = t >> 4;
    int row = blockIdx.x * 16 + rloc;

    ((float4*)d_agg)[row * HV + lane] = f4zero();

    if (row < NN) {
        float4 acc = bs[lane];
        const float* xr = x + row * INF_;
        #pragma unroll
        for (int k = 0; k < INF_; k++) {
            float xv = __ldg(xr + k);
            f4fma(acc, xv, Ws[k * HV + lane]);
        }
        ((float4*)d_h)[row * HV + lane] = acc;
        ((uint2*)d_h16)[row * HV + lane] = f4_to_h4(acc);
    }
}

// ---------------- edge kernel: agg[dst] += relu(h16[src] + ea @ We + be) ---
// 128 edges/block, 8 per 16-thread group; int4 index loads; 8 gathers in
// flight per thread.
__global__ void __launch_bounds__(256) edge_kernel(const int* __restrict__ ei,
                                                   const float* __restrict__ eattr,
                                                   const float* __restrict__ eW,
                                                   const float* __restrict__ eb) {
    __shared__ __align__(16) float4 Ws[EDIM * HV];
    __shared__ __align__(16) float4 bs[HV];
    int t = threadIdx.x;
    if (t < EDIM * HV) Ws[t] = ((const float4*)eW)[t];
    if (t < HV) bs[t] = ((const float4*)eb)[t];
    __syncthreads();

    int e0   = blockIdx.x * EPB + (t >> 4) * 8;   // first of 8 consecutive edges
    int lane = t & 15;

    int4 sa = __ldg((const int4*)(ei) + (e0 >> 2));
    int4 sb = __ldg((const int4*)(ei) + (e0 >> 2) + 1);
    int4 da = __ldg((const int4*)(ei + NE) + (e0 >> 2));
    int4 db = __ldg((const int4*)(ei + NE) + (e0 >> 2) + 1);
    int src[8] = {sa.x, sa.y, sa.z, sa.w, sb.x, sb.y, sb.z, sb.w};
    int dst[8] = {da.x, da.y, da.z, da.w, db.x, db.y, db.z, db.w};

    uint2 hr[8];
    #pragma unroll
    for (int j = 0; j < 8; j++)
        hr[j] = __ldg((const uint2*)d_h16 + src[j] * HV + lane);

    float4 a[8];
    #pragma unroll
    for (int j = 0; j < 8; j++) a[j] = __ldg((const float4*)eattr + e0 + j);

    float4 w0 = Ws[0 * HV + lane], w1 = Ws[1 * HV + lane];
    float4 w2 = Ws[2 * HV + lane], w3 = Ws[3 * HV + lane];
    float4 bv = bs[lane];

    #pragma unroll
    for (int j = 0; j < 8; j++) {
        float4 v = bv;
        f4fma(v, a[j].x, w0);
        f4fma(v, a[j].y, w1);
        f4fma(v, a[j].z, w2);
        f4fma(v, a[j].w, w3);
        float4 m = f4relu_add(v, h4_to_f4(hr[j]));
        red_add4((float4*)d_agg + dst[j] * HV + lane, m);
    }
}

// ---------------- fused node MLP: both GEMMs, z tile smem-resident ---------
// z = (1+eps)*h + agg ; t = relu(BN1(z@W1+b1)) [smem] ; h' = relu(BN2(t@W2+b2))
// Ws buffer reused for W1 then W2. do_pn=1: PN stats + agg re-zero;
// do_pn=0 (last layer): fused global add pool.
__global__ void __launch_bounds__(256) mlp_fused_kernel(
    const float* __restrict__ W1, const float* __restrict__ b1,
    const float* __restrict__ g1, const float* __restrict__ be1,
    const float* __restrict__ rm1, const float* __restrict__ rv1,
    const float* __restrict__ W2, const float* __restrict__ b2,
    const float* __restrict__ g2, const float* __restrict__ be2,
    const float* __restrict__ rm2, const float* __restrict__ rv2,
    const float* __restrict__ epsp, const int* __restrict__ batch, int do_pn)
{
    __shared__ __align__(16) float Ws[H * H];
    __shared__ __align__(16) float zs[64 * H];

    int t = threadIdx.x;
    int c4 = t & 15, rg = t >> 4;
    int c0 = c4 * 4;
    int R0 = blockIdx.x * 64;

    // --- phase 1 loads: W1, z inputs, BN1 params ---
    float4 wv[4];
    #pragma unroll
    for (int s = 0; s < 4; s++) wv[s] = __ldg((const float4*)W1 + t + 256 * s);

    float4 gv  = __ldg((const float4*)(g1 + c0));
    float4 rvv = __ldg((const float4*)(rv1 + c0));
    float4 bv  = __ldg((const float4*)(b1 + c0));
    float4 bev = __ldg((const float4*)(be1 + c0));
    float4 rmv = __ldg((const float4*)(rm1 + c0));
    float epv = 1.0f + __ldg(epsp);

    float4 zst[4];
    #pragma unroll
    for (int s = 0; s < 4; s++) {
        int gi = R0 * HV + t + 256 * s;
        float4 hv = __ldg((const float4*)d_h + gi);
        float4 av = __ldg((const float4*)d_agg + gi);
        zst[s] = make_float4(fmaf(epv, hv.x, av.x), fmaf(epv, hv.y, av.y),
                             fmaf(epv, hv.z, av.z), fmaf(epv, hv.w, av.w));
        if (do_pn) ((float4*)d_agg)[gi] = f4zero();
    }

    float4 sc, bb;
    sc.x = gv.x * rsqrtf(rvv.x + BN_EPS);
    sc.y = gv.y * rsqrtf(rvv.y + BN_EPS);
    sc.z = gv.z * rsqrtf(rvv.z + BN_EPS);
    sc.w = gv.w * rsqrtf(rvv.w + BN_EPS);
    bb.x = fmaf(bv.x - rmv.x, sc.x, bev.x);
    bb.y = fmaf(bv.y - rmv.y, sc.y, bev.y);
    bb.z = fmaf(bv.z - rmv.z, sc.z, bev.z);
    bb.w = fmaf(bv.w - rmv.w, sc.w, bev.w);

    #pragma unroll
    for (int s = 0; s < 4; s++) {
        float4 w = wv[s];
        w.x *= sc.x; w.y *= sc.y; w.z *= sc.z; w.w *= sc.w;
        ((float4*)Ws)[t + 256 * s] = w;
        ((float4*)zs)[t + 256 * s] = zst[s];
    }
    __syncthreads();

    // --- GEMM1 ---
    float4 acc[4];
    gemm64(Ws, zs, rg, c4, acc);
    float4 t0 = f4relu_add(acc[0], bb);
    float4 t1 = f4relu_add(acc[1], bb);
    float4 t2 = f4relu_add(acc[2], bb);
    float4 t3 = f4relu_add(acc[3], bb);

    // --- phase 2 loads (latency hides under barrier wait) ---
    #pragma unroll
    for (int s = 0; s < 4; s++) wv[s] = __ldg((const float4*)W2 + t + 256 * s);
    gv  = __ldg((const float4*)(g2 + c0));
    rvv = __ldg((const float4*)(rv2 + c0));
    bv  = __ldg((const float4*)(b2 + c0));
    bev = __ldg((const float4*)(be2 + c0));
    rmv = __ldg((const float4*)(rm2 + c0));

    __syncthreads();   // all reads of Ws/zs (GEMM1) complete

    sc.x = gv.x * rsqrtf(rvv.x + BN_EPS);
    sc.y = gv.y * rsqrtf(rvv.y + BN_EPS);
    sc.z = gv.z * rsqrtf(rvv.z + BN_EPS);
    sc.w = gv.w * rsqrtf(rvv.w + BN_EPS);
    bb.x = fmaf(bv.x - rmv.x, sc.x, bev.x);
    bb.y = fmaf(bv.y - rmv.y, sc.y, bev.y);
    bb.z = fmaf(bv.z - rmv.z, sc.z, bev.z);
    bb.w = fmaf(bv.w - rmv.w, sc.w, bev.w);

    // stage t into zs (each thread owns its 4x4 patch) and W2 into Ws
    *(float4*)&zs[(rg * 4 + 0) * H + c0] = t0;
    *(float4*)&zs[(rg * 4 + 1) * H + c0] = t1;
    *(float4*)&zs[(rg * 4 + 2) * H + c0] = t2;
    *(float4*)&zs[(rg * 4 + 3) * H + c0] = t3;
    #pragma unroll
    for (int s = 0; s < 4; s++) {
        float4 w = wv[s];
        w.x *= sc.x; w.y *= sc.y; w.z *= sc.z; w.w *= sc.w;
        ((float4*)Ws)[t + 256 * s] = w;
    }
    __syncthreads();

    // --- GEMM2 ---
    gemm64(Ws, zs, rg, c4, acc);

    int row0 = R0 + rg * 4;
    #pragma unroll
    for (int r = 0; r < 4; r++) {
        int row = row0 + r;
        float4 hv = f4relu_add(acc[r], bb);
        if (row < NN) ((float4*)d_h)[row * HV + c4] = hv;
        int gg = (row < NN) ? __ldg(batch + row) : 0;
        if (do_pn) {
            if (row < NN) red_add4(&((float4*)d_gsum)[gg * HV + c4], hv);
            float v = (row < NN) ? (hv.x*hv.x + hv.y*hv.y + hv.z*hv.z + hv.w*hv.w) : 0.f;
            #pragma unroll
            for (int o = 1; o < 16; o <<= 1) v += __shfl_xor_sync(0xffffffffu, v, o);
            if (c4 == 0 && row < NN) atomicAdd(&d_gss[gg], v);
        } else {
            if (row < NN) red_add4(&((float4*)d_pool)[gg * HV + c4], hv);
        }
    }
}

// ---------------- PairNorm per-graph mean & inverse denom; self-re-zeros ---
__global__ void meaninv_kernel() {
    int g = blockIdx.x, c = threadIdx.x;     // 64 threads
    float cnt = d_gcnt[g];
    float s = d_gsum[g * H + c];
    d_gsum[g * H + c] = 0.f;
    float mean = s / cnt;
    d_mean[g * H + c] = mean;
    float part = mean * s;
    #pragma unroll
    for (int o = 16; o; o >>= 1) part += __shfl_down_sync(0xffffffffu, part, o);
    __shared__ float red[2];
    if ((c & 31) == 0) red[c >> 5] = part;
    __syncthreads();
    if (c == 0) {
        float ss = d_gss[g];
        d_gss[g] = 0.f;
        float var = (ss - (red[0] + red[1])) / cnt;
        d_invd[g] = rsqrtf(PN_EPS + var);
    }
}

// ---------------- PairNorm apply (also writes fp16 shadow) -----------------
__global__ void __launch_bounds__(256) norm_kernel(const int* __restrict__ batch) {
    int idx = blockIdx.x * 256 + threadIdx.x;    // exactly NN*HV
    int row = idx >> 4, ln = idx & 15;
    int g = __ldg(batch + row);
    float4 hv = ((const float4*)d_h)[idx];
    float4 m = ((const float4*)d_mean)[g * HV + ln];
    float id = d_invd[g];
    hv.x = (hv.x - m.x) * id;
    hv.y = (hv.y - m.y) * id;
    hv.z = (hv.z - m.z) * id;
    hv.w = (hv.w - m.w) * id;
    ((float4*)d_h)[idx] = hv;
    ((uint2*)d_h16)[idx] = f4_to_h4(hv);
}

// ---------------- classifier; self-re-zeros pool ---------------------------
__global__ void cls_kernel(const float* __restrict__ W, const float* __restrict__ b,
                           float* __restrict__ out) {
    int g = blockIdx.x, c = threadIdx.x;     // 64 threads
    float p = d_pool[g * H + c];
    d_pool[g * H + c] = 0.f;
    float a = p * W[c * NOUT + 0];
    float bb = p * W[c * NOUT + 1];
    #pragma unroll
    for (int o = 16; o; o >>= 1) {
        a  += __shfl_down_sync(0xffffffffu, a, o);
        bb += __shfl_down_sync(0xffffffffu, bb, o);
    }
    __shared__ float sa[2], sb[2];
    if ((c & 31) == 0) { sa[c >> 5] = a; sb[c >> 5] = bb; }
    __syncthreads();
    if (c == 0) {
        out[g * NOUT + 0] = sa[0] + sa[1] + b[0];
        out[g * NOUT + 1] = sb[0] + sb[1] + b[1];
    }
}

// ---------------------------------------------------------------------------
extern "C" void kernel_launch(void* const* d_in, const int* in_sizes, int n_in,
                              void* d_out, int out_size) {
    const float* x        = (const float*)d_in[0];
    const int*   ei       = (const int*)  d_in[1];
    const float* eattr    = (const float*)d_in[2];
    const int*   batch    = (const int*)  d_in[3];
    const float* lin_W    = (const float*)d_in[4];
    const float* lin_b    = (const float*)d_in[5];
    const float* edge_W   = (const float*)d_in[6];
    const float* edge_b   = (const float*)d_in[7];
    const float* mlp_W1   = (const float*)d_in[8];
    const float* mlp_b1   = (const float*)d_in[9];
    const float* mbn_g    = (const float*)d_in[10];
    const float* mbn_b    = (const float*)d_in[11];
    const float* mbn_rm   = (const float*)d_in[12];
    const float* mbn_rv   = (const float*)d_in[13];
    const float* mlp_W2   = (const float*)d_in[14];
    const float* mlp_b2   = (const float*)d_in[15];
    const float* eps      = (const float*)d_in[16];
    const float* bn_g     = (const float*)d_in[17];
    const float* bn_b     = (const float*)d_in[18];
    const float* bn_rm    = (const float*)d_in[19];
    const float* bn_rv    = (const float*)d_in[20];
    const float* cls_W    = (const float*)d_in[21];
    const float* cls_b    = (const float*)d_in[22];
    float* out = (float*)d_out;

    count_kernel<<<2, 256>>>(batch);
    lin_in_kernel<<<NPAD / 16, 256>>>(x, lin_W, lin_b);

    for (int i = 0; i < NL; i++) {
        edge_kernel<<<NE / EPB, 256>>>(ei, eattr, edge_W + i * EDIM * H, edge_b + i * H);
        int do_pn = (i < NL - 1) ? 1 : 0;
        mlp_fused_kernel<<<NPAD / 64, 256>>>(
            mlp_W1 + i * H * H, mlp_b1 + i * H,
            mbn_g + i * H, mbn_b + i * H, mbn_rm + i * H, mbn_rv + i * H,
            mlp_W2 + i * H * H, mlp_b2 + i * H,
            bn_g + i * H, bn_b + i * H, bn_rm + i * H, bn_rv + i * H,
            eps + i, batch, do_pn);
        if (do_pn) {
            meaninv_kernel<<<NG, H>>>();
            norm_kernel<<<(NN * HV) / 256, 256>>>(batch);
        }
    }

    cls_kernel<<<NG, H>>>(cls_W, cls_b, out);
}